// round 1
// baseline (speedup 1.0000x reference)
#include <cuda_runtime.h>
#include <cuda_bf16.h>

// Shapes
#define BB   4
#define CC   64
#define DCC  16
#define FF   256
#define TT   384
#define NN   (FF*TT)          // 98304
#define PP   (BB*NN)          // 393216

// ---------------------------------------------------------------------------
// Scratch (device globals; allocation is forbidden)
// ---------------------------------------------------------------------------
__device__ float g_fqkv   [(size_t)BB*48*NN];  // [b][c48][f][t]   natural
__device__ float g_fqkv_t [(size_t)BB*48*NN];  // [b][t][c48][f]   transposed
__device__ float g_tqk    [(size_t)BB*32*NN];  // [b][c32][f][t]   natural
__device__ float g_fout_t [(size_t)BB*16*NN];  // [b][t][c16][f]
__device__ float g_fout   [(size_t)BB*16*NN];  // [b][c16][f][t]
__device__ float g_tout   [(size_t)BB*16*NN];  // [b][c16][f][t]

// ---------------------------------------------------------------------------
// FMA-only exp (avoids MUFU.EX2 serialization). x <= 0 expected.
// exp(x) = 2^(x*log2e); round to nearest int exponent, degree-5 poly on the
// residual (|u| <= ln2/2), rel err ~2e-6.
// ---------------------------------------------------------------------------
__device__ __forceinline__ float fexp(float x) {
    float t  = fmaxf(x * 1.4426950408889634f, -126.0f);
    float fi = rintf(t);
    float u  = (t - fi) * 0.6931471805599453f;
    float p  = 1.f + u*(1.f + u*(0.5f + u*(0.1666666667f + u*(0.0416666667f + u*0.0083333333f))));
    return __int_as_float(((int)fi + 127) << 23) * p;
}

__device__ __forceinline__ float dot16(const float (&q)[16], const float* kr) {
    const float4* kp = (const float4*)kr;
    float4 a = kp[0], b = kp[1], c = kp[2], d = kp[3];
    return q[ 0]*a.x + q[ 1]*a.y + q[ 2]*a.z + q[ 3]*a.w
         + q[ 4]*b.x + q[ 5]*b.y + q[ 6]*b.z + q[ 7]*b.w
         + q[ 8]*c.x + q[ 9]*c.y + q[10]*c.z + q[11]*c.w
         + q[12]*d.x + q[13]*d.y + q[14]*d.z + q[15]*d.w;
}

// ---------------------------------------------------------------------------
// Kernel 1: fused fqkv (48ch) + tqk (32ch) conv1x1 + BN + PReLU
// ---------------------------------------------------------------------------
__global__ __launch_bounds__(256) void k_qkv(
    const float* __restrict__ x,
    const float* __restrict__ fw, const float* __restrict__ fg,
    const float* __restrict__ fb, const float* __restrict__ fm,
    const float* __restrict__ fv, const float* __restrict__ fa,
    const float* __restrict__ tw, const float* __restrict__ tg,
    const float* __restrict__ tb, const float* __restrict__ tm,
    const float* __restrict__ tvv, const float* __restrict__ ta)
{
    __shared__ float ws[80*64];
    __shared__ float sa[80], sbb[80], sal[80];
    int tid = threadIdx.x;
    for (int i = tid; i < 48*64; i += 256) ws[i] = fw[i];
    for (int i = tid; i < 32*64; i += 256) ws[48*64 + i] = tw[i];
    if (tid < 80) {
        float g, be, mn, vr, al;
        if (tid < 48) { g=fg[tid]; be=fb[tid]; mn=fm[tid]; vr=fv[tid]; al=fa[tid]; }
        else { int o=tid-48; g=tg[o]; be=tb[o]; mn=tm[o]; vr=tvv[o]; al=ta[o]; }
        float a = g * rsqrtf(vr + 1e-5f);
        sa[tid] = a; sbb[tid] = be - mn*a; sal[tid] = al;
    }
    __syncthreads();

    size_t p   = (size_t)blockIdx.x*256 + tid;
    int    b   = (int)(p / NN);
    int    rem = (int)(p % NN);

    float xv[64];
    const float* xb = x + (size_t)b*CC*NN + rem;
    #pragma unroll
    for (int c = 0; c < 64; c++) xv[c] = xb[(size_t)c*NN];

    for (int o = 0; o < 80; o++) {
        const float4* wp = (const float4*)(ws + o*64);
        float acc = 0.f;
        #pragma unroll
        for (int c4 = 0; c4 < 16; c4++) {
            float4 w = wp[c4];
            acc += w.x*xv[4*c4] + w.y*xv[4*c4+1] + w.z*xv[4*c4+2] + w.w*xv[4*c4+3];
        }
        float yn = acc*sa[o] + sbb[o];
        float r  = yn >= 0.f ? yn : sal[o]*yn;
        if (o < 48) g_fqkv[((size_t)b*48 + o     )*NN + rem] = r;
        else        g_tqk [((size_t)b*32 + (o-48))*NN + rem] = r;
    }
}

// ---------------------------------------------------------------------------
// Transposes (32x32 smem tiles, coalesced both ways)
// ---------------------------------------------------------------------------
__global__ void k_trans_qkv() {  // [b][cf=12288][t=384] -> [b][t][cf]
    __shared__ float tile[32][33];
    int b = blockIdx.z;
    size_t base = (size_t)b * 12288 * 384;
    int r0 = blockIdx.y*32, q0 = blockIdx.x*32;
    for (int i = threadIdx.y; i < 32; i += 8)
        tile[i][threadIdx.x] = g_fqkv[base + (size_t)(r0+i)*384 + q0 + threadIdx.x];
    __syncthreads();
    for (int i = threadIdx.y; i < 32; i += 8)
        g_fqkv_t[base + (size_t)(q0+i)*12288 + r0 + threadIdx.x] = tile[threadIdx.x][i];
}

__global__ void k_trans_fout() { // [b][t=384][cf=4096] -> [b][cf][t]
    __shared__ float tile[32][33];
    int b = blockIdx.z;
    size_t base = (size_t)b * 4096 * 384;
    int r0 = blockIdx.y*32, q0 = blockIdx.x*32;   // r over t, q over cf
    for (int i = threadIdx.y; i < 32; i += 8)
        tile[i][threadIdx.x] = g_fout_t[base + (size_t)(r0+i)*4096 + q0 + threadIdx.x];
    __syncthreads();
    for (int i = threadIdx.y; i < 32; i += 8)
        g_fout[base + (size_t)(q0+i)*384 + r0 + threadIdx.x] = tile[threadIdx.x][i];
}

// ---------------------------------------------------------------------------
// Kernel 3: frequency attention. Block = (t, b); thread = f row.
// ---------------------------------------------------------------------------
__global__ __launch_bounds__(256) void k_fattn() {
    __shared__ float ks[256*16];
    __shared__ float vs[256*16];
    int t = blockIdx.x, b = blockIdx.y;
    int tid = threadIdx.x;
    const float* base = g_fqkv_t + (size_t)(b*TT + t) * (48*FF);

    for (int i = tid; i < 4096; i += 256) {
        int c = i >> 8, y = i & 255;
        ks[y*16 + c] = base[(16+c)*FF + y];
        vs[y*16 + c] = base[(32+c)*FF + y];
    }
    float q[16];
    #pragma unroll
    for (int c = 0; c < 16; c++) q[c] = base[c*FF + tid] * 0.25f;  // 1/sqrt(DC)
    __syncthreads();

    float m = -1e30f;
    for (int y = 0; y < 256; y++) {
        float s = dot16(q, ks + y*16);
        m = fmaxf(m, s);
    }
    float sum = 0.f;
    float acc[16];
    #pragma unroll
    for (int c = 0; c < 16; c++) acc[c] = 0.f;
    for (int y = 0; y < 256; y++) {
        float s = dot16(q, ks + y*16);
        float p = fexp(s - m);
        sum += p;
        const float4* vp = (const float4*)(vs + y*16);
        float4 v0=vp[0], v1=vp[1], v2=vp[2], v3=vp[3];
        acc[ 0]+=p*v0.x; acc[ 1]+=p*v0.y; acc[ 2]+=p*v0.z; acc[ 3]+=p*v0.w;
        acc[ 4]+=p*v1.x; acc[ 5]+=p*v1.y; acc[ 6]+=p*v1.z; acc[ 7]+=p*v1.w;
        acc[ 8]+=p*v2.x; acc[ 9]+=p*v2.y; acc[10]+=p*v2.z; acc[11]+=p*v2.w;
        acc[12]+=p*v3.x; acc[13]+=p*v3.y; acc[14]+=p*v3.z; acc[15]+=p*v3.w;
    }
    float inv = 1.0f / sum;
    float* op = g_fout_t + (size_t)(b*TT + t) * (16*FF);
    #pragma unroll
    for (int c = 0; c < 16; c++) op[c*FF + tid] = acc[c] * inv;
}

// ---------------------------------------------------------------------------
// Kernel 5: time attention (causal). Block = (f, b); thread = t row.
// ---------------------------------------------------------------------------
__global__ __launch_bounds__(384) void k_tattn() {
    __shared__ float ks[384*16];   // kt   [y][c]
    __shared__ float vs[384*16];   // fout [y][c]
    int f = blockIdx.x, b = blockIdx.y;
    int tid = threadIdx.x;  // t

    const float* ktb = g_tqk  + (((size_t)b*32 + 16)*FF + f)*TT;
    const float* vb  = g_fout + (((size_t)b*16     )*FF + f)*TT;
    for (int i = tid; i < 6144; i += 384) {
        int c = i / 384, y = i % 384;
        ks[y*16 + c] = ktb[(size_t)c*NN + y];
        vs[y*16 + c] = vb [(size_t)c*NN + y];
    }
    float q[16];
    const float* qb = g_tqk + (((size_t)b*32)*FF + f)*TT;
    #pragma unroll
    for (int c = 0; c < 16; c++) q[c] = qb[(size_t)c*NN + tid] * 0.25f;
    __syncthreads();

    int t = tid;
    float m = -1e30f;
    for (int y = 0; y <= t; y++) {
        float s = dot16(q, ks + y*16);
        m = fmaxf(m, s);
    }
    float sum = 0.f;
    float acc[16];
    #pragma unroll
    for (int c = 0; c < 16; c++) acc[c] = 0.f;
    for (int y = 0; y <= t; y++) {
        float s = dot16(q, ks + y*16);
        float p = fexp(s - m);
        sum += p;
        const float4* vp = (const float4*)(vs + y*16);
        float4 v0=vp[0], v1=vp[1], v2=vp[2], v3=vp[3];
        acc[ 0]+=p*v0.x; acc[ 1]+=p*v0.y; acc[ 2]+=p*v0.z; acc[ 3]+=p*v0.w;
        acc[ 4]+=p*v1.x; acc[ 5]+=p*v1.y; acc[ 6]+=p*v1.z; acc[ 7]+=p*v1.w;
        acc[ 8]+=p*v2.x; acc[ 9]+=p*v2.y; acc[10]+=p*v2.z; acc[11]+=p*v2.w;
        acc[12]+=p*v3.x; acc[13]+=p*v3.y; acc[14]+=p*v3.z; acc[15]+=p*v3.w;
    }
    float inv = 1.0f / sum;
    float* op = g_tout + (((size_t)b*16)*FF + f)*TT + t;
    #pragma unroll
    for (int c = 0; c < 16; c++) op[(size_t)c*NN] = acc[c] * inv;
}

// ---------------------------------------------------------------------------
// Kernel 6: proj conv1x1 (64<-16) + BN + PReLU + residual
// ---------------------------------------------------------------------------
__global__ __launch_bounds__(256) void k_proj(
    const float* __restrict__ x,
    const float* __restrict__ pw, const float* __restrict__ pg,
    const float* __restrict__ pb, const float* __restrict__ pm,
    const float* __restrict__ pv, const float* __restrict__ pa,
    float* __restrict__ out)
{
    __shared__ float ws[64*16];
    __shared__ float sa[64], sbb[64], sal[64];
    int tid = threadIdx.x;
    for (int i = tid; i < 1024; i += 256) ws[i] = pw[i];
    if (tid < 64) {
        float a = pg[tid] * rsqrtf(pv[tid] + 1e-5f);
        sa[tid] = a; sbb[tid] = pb[tid] - pm[tid]*a; sal[tid] = pa[tid];
    }
    __syncthreads();

    size_t p   = (size_t)blockIdx.x*256 + tid;
    int    b   = (int)(p / NN);
    int    rem = (int)(p % NN);

    float tv[16];
    #pragma unroll
    for (int c = 0; c < 16; c++) tv[c] = g_tout[((size_t)b*16 + c)*NN + rem];

    const float* xb = x   + (size_t)b*CC*NN + rem;
    float*       ob = out + (size_t)b*CC*NN + rem;
    for (int o = 0; o < 64; o++) {
        const float4* wp = (const float4*)(ws + o*16);
        float4 w0=wp[0], w1=wp[1], w2=wp[2], w3=wp[3];
        float acc = w0.x*tv[ 0]+w0.y*tv[ 1]+w0.z*tv[ 2]+w0.w*tv[ 3]
                  + w1.x*tv[ 4]+w1.y*tv[ 5]+w1.z*tv[ 6]+w1.w*tv[ 7]
                  + w2.x*tv[ 8]+w2.y*tv[ 9]+w2.z*tv[10]+w2.w*tv[11]
                  + w3.x*tv[12]+w3.y*tv[13]+w3.z*tv[14]+w3.w*tv[15];
        float yn = acc*sa[o] + sbb[o];
        float r  = yn >= 0.f ? yn : sal[o]*yn;
        ob[(size_t)o*NN] = r + xb[(size_t)o*NN];
    }
}

// ---------------------------------------------------------------------------
extern "C" void kernel_launch(void* const* d_in, const int* in_sizes, int n_in,
                              void* d_out, int out_size)
{
    const float* x   = (const float*)d_in[0];
    const float* fw  = (const float*)d_in[1];
    const float* fg  = (const float*)d_in[2];
    const float* fb  = (const float*)d_in[3];
    const float* fm  = (const float*)d_in[4];
    const float* fv  = (const float*)d_in[5];
    const float* fa  = (const float*)d_in[6];
    const float* tw  = (const float*)d_in[7];
    const float* tg  = (const float*)d_in[8];
    const float* tb  = (const float*)d_in[9];
    const float* tm  = (const float*)d_in[10];
    const float* tvv = (const float*)d_in[11];
    const float* ta  = (const float*)d_in[12];
    const float* pw  = (const float*)d_in[13];
    const float* pg  = (const float*)d_in[14];
    const float* pb  = (const float*)d_in[15];
    const float* pm  = (const float*)d_in[16];
    const float* pv  = (const float*)d_in[17];
    const float* pa  = (const float*)d_in[18];
    float*       out = (float*)d_out;

    // 1) fused qkv convs + BN + PReLU
    k_qkv<<<PP/256, 256>>>(x, fw, fg, fb, fm, fv, fa, tw, tg, tb, tm, tvv, ta);

    // 2) transpose fqkv: [b][cf][t] -> [b][t][cf]
    k_trans_qkv<<<dim3(384/32, 12288/32, BB), dim3(32,8)>>>();

    // 3) frequency attention
    k_fattn<<<dim3(TT, BB), 256>>>();

    // 4) transpose f_out: [b][t][cf] -> [b][cf][t]
    k_trans_fout<<<dim3(4096/32, 384/32, BB), dim3(32,8)>>>();

    // 5) time attention (causal)
    k_tattn<<<dim3(FF, BB), 384>>>();

    // 6) proj + BN + PReLU + residual
    k_proj<<<PP/256, 256>>>(x, pw, pg, pb, pm, pv, pa, out);
}

// round 2
// speedup vs baseline: 1.4770x; 1.4770x over previous
#include <cuda_runtime.h>
#include <cuda_bf16.h>

// Shapes
#define BB   4
#define CC   64
#define DCC  16
#define FF   256
#define TT   384
#define NN   (FF*TT)          // 98304
#define PP   (BB*NN)          // 393216

typedef unsigned long long u64;

// ---------------------------------------------------------------------------
// Scratch (device globals; allocation is forbidden)
// ---------------------------------------------------------------------------
__device__ float g_fqkv   [(size_t)BB*48*NN];  // [b][c48][f][t]   natural
__device__ float g_fqkv_t [(size_t)BB*48*NN];  // [b][t][c48][f]   transposed
__device__ float g_tqk    [(size_t)BB*32*NN];  // [b][c32][f][t]   natural
__device__ float g_fout_t [(size_t)BB*16*NN];  // [b][t][c16][f]
__device__ float g_fout   [(size_t)BB*16*NN];  // [b][c16][f][t]
__device__ float g_tout   [(size_t)BB*16*NN];  // [b][c16][f][t]

// ---------------------------------------------------------------------------
// Packed f32x2 helpers (Blackwell FFMA2 — 2 results per issue slot)
// ---------------------------------------------------------------------------
__device__ __forceinline__ u64 fma2(u64 a, u64 b, u64 c) {
    u64 d;
    asm("fma.rn.f32x2 %0, %1, %2, %3;" : "=l"(d) : "l"(a), "l"(b), "l"(c));
    return d;
}
__device__ __forceinline__ u64 add2(u64 a, u64 b) {
    u64 d;
    asm("add.rn.f32x2 %0, %1, %2;" : "=l"(d) : "l"(a), "l"(b));
    return d;
}
__device__ __forceinline__ u64 pack2(float lo, float hi) {
    u64 d;
    asm("mov.b64 %0, {%1, %2};" : "=l"(d) : "f"(lo), "f"(hi));
    return d;
}
__device__ __forceinline__ void unpack2(u64 a, float& lo, float& hi) {
    asm("mov.b64 {%0, %1}, %2;" : "=f"(lo), "=f"(hi) : "l"(a));
}
__device__ __forceinline__ float hsum2(u64 a) {
    float lo, hi; unpack2(a, lo, hi); return lo + hi;
}

// ---------------------------------------------------------------------------
// FMA-only exp: no MUFU, no F2I/I2F cvts (magic-constant rounding).
// Valid for |x| small (scores here are |x| <~ 10). rel err ~2e-6.
// ---------------------------------------------------------------------------
__device__ __forceinline__ float fexp(float x) {
    float t  = x * 1.4426950408889634f;
    float z  = t + 12582912.0f;                 // 2^23 + 2^22: round-to-nearest
    int   e  = __float_as_int(z) - 0x4B400000;  // = round(t) as integer
    float fi = z - 12582912.0f;
    float u  = (t - fi) * 0.6931471805599453f;
    float p  = fmaf(u, 0.0083333333f, 0.0416666667f);
    p = fmaf(u, p, 0.1666666667f);
    p = fmaf(u, p, 0.5f);
    p = fmaf(u, p, 1.0f);
    p = fmaf(u, p, 1.0f);
    return __int_as_float((e + 127) << 23) * p;
}

// Packed dot of 16 floats: q pre-packed as 8 u64 pairs, k row 16B-aligned.
__device__ __forceinline__ float dot16p(const u64 (&q)[8], const float* kr) {
    const ulonglong2* kp = (const ulonglong2*)kr;
    ulonglong2 k0 = kp[0], k1 = kp[1], k2 = kp[2], k3 = kp[3];
    u64 a0 = fma2(q[0], k0.x, 0), a1 = fma2(q[1], k0.y, 0);
    a0 = fma2(q[2], k1.x, a0);  a1 = fma2(q[3], k1.y, a1);
    a0 = fma2(q[4], k2.x, a0);  a1 = fma2(q[5], k2.y, a1);
    a0 = fma2(q[6], k3.x, a0);  a1 = fma2(q[7], k3.y, a1);
    return hsum2(add2(a0, a1));
}

// ---------------------------------------------------------------------------
// Kernel 1: fused fqkv (48ch) + tqk (32ch) conv1x1 + BN + PReLU (packed FMA)
// ---------------------------------------------------------------------------
__global__ __launch_bounds__(256) void k_qkv(
    const float* __restrict__ x,
    const float* __restrict__ fw, const float* __restrict__ fg,
    const float* __restrict__ fb, const float* __restrict__ fm,
    const float* __restrict__ fv, const float* __restrict__ fa,
    const float* __restrict__ tw, const float* __restrict__ tg,
    const float* __restrict__ tb, const float* __restrict__ tm,
    const float* __restrict__ tvv, const float* __restrict__ ta)
{
    __shared__ float ws[80*64];
    __shared__ float sa[80], sbb[80], sal[80];
    int tid = threadIdx.x;
    for (int i = tid; i < 48*64; i += 256) ws[i] = fw[i];
    for (int i = tid; i < 32*64; i += 256) ws[48*64 + i] = tw[i];
    if (tid < 80) {
        float g, be, mn, vr, al;
        if (tid < 48) { g=fg[tid]; be=fb[tid]; mn=fm[tid]; vr=fv[tid]; al=fa[tid]; }
        else { int o=tid-48; g=tg[o]; be=tb[o]; mn=tm[o]; vr=tvv[o]; al=ta[o]; }
        float a = g * rsqrtf(vr + 1e-5f);
        sa[tid] = a; sbb[tid] = be - mn*a; sal[tid] = al;
    }
    __syncthreads();

    size_t p   = (size_t)blockIdx.x*256 + tid;
    int    b   = (int)(p / NN);
    int    rem = (int)(p % NN);

    u64 xv[32];
    const float* xb = x + (size_t)b*CC*NN + rem;
    #pragma unroll
    for (int c = 0; c < 32; c++)
        xv[c] = pack2(xb[(size_t)(2*c)*NN], xb[(size_t)(2*c+1)*NN]);

    for (int o = 0; o < 80; o++) {
        const ulonglong2* wp = (const ulonglong2*)(ws + o*64);
        u64 a0 = 0, a1 = 0;
        #pragma unroll
        for (int i = 0; i < 16; i++) {
            ulonglong2 w = wp[i];
            a0 = fma2(xv[2*i],   w.x, a0);
            a1 = fma2(xv[2*i+1], w.y, a1);
        }
        float acc = hsum2(add2(a0, a1));
        float yn = acc*sa[o] + sbb[o];
        float r  = yn >= 0.f ? yn : sal[o]*yn;
        if (o < 48) g_fqkv[((size_t)b*48 + o     )*NN + rem] = r;
        else        g_tqk [((size_t)b*32 + (o-48))*NN + rem] = r;
    }
}

// ---------------------------------------------------------------------------
// Transposes (32x32 smem tiles, coalesced both ways)
// ---------------------------------------------------------------------------
__global__ void k_trans_qkv() {  // [b][cf=12288][t=384] -> [b][t][cf]
    __shared__ float tile[32][33];
    int b = blockIdx.z;
    size_t base = (size_t)b * 12288 * 384;
    int r0 = blockIdx.y*32, q0 = blockIdx.x*32;
    for (int i = threadIdx.y; i < 32; i += 8)
        tile[i][threadIdx.x] = g_fqkv[base + (size_t)(r0+i)*384 + q0 + threadIdx.x];
    __syncthreads();
    for (int i = threadIdx.y; i < 32; i += 8)
        g_fqkv_t[base + (size_t)(q0+i)*12288 + r0 + threadIdx.x] = tile[threadIdx.x][i];
}

__global__ void k_trans_fout() { // [b][t=384][cf=4096] -> [b][cf][t]
    __shared__ float tile[32][33];
    int b = blockIdx.z;
    size_t base = (size_t)b * 4096 * 384;
    int r0 = blockIdx.y*32, q0 = blockIdx.x*32;   // r over t, q over cf
    for (int i = threadIdx.y; i < 32; i += 8)
        tile[i][threadIdx.x] = g_fout_t[base + (size_t)(r0+i)*4096 + q0 + threadIdx.x];
    __syncthreads();
    for (int i = threadIdx.y; i < 32; i += 8)
        g_fout[base + (size_t)(q0+i)*384 + r0 + threadIdx.x] = tile[threadIdx.x][i];
}

// ---------------------------------------------------------------------------
// Kernel 3: frequency attention. Block = (t, b); thread = f row.
// Single pass, no max subtraction (scores bounded small), packed FMA.
// ---------------------------------------------------------------------------
__global__ __launch_bounds__(256) void k_fattn() {
    __shared__ float ks[256*16];
    __shared__ float vs[256*16];
    int t = blockIdx.x, b = blockIdx.y;
    int tid = threadIdx.x;
    const float* base = g_fqkv_t + (size_t)(b*TT + t) * (48*FF);

    for (int i = tid; i < 4096; i += 256) {
        int c = i >> 8, y = i & 255;
        ks[y*16 + c] = base[(16+c)*FF + y];
        vs[y*16 + c] = base[(32+c)*FF + y];
    }
    u64 q[8];
    #pragma unroll
    for (int c = 0; c < 8; c++)
        q[c] = pack2(base[(2*c)*FF + tid] * 0.25f, base[(2*c+1)*FF + tid] * 0.25f);
    __syncthreads();

    float sum = 0.f;
    u64 acc[8];
    #pragma unroll
    for (int c = 0; c < 8; c++) acc[c] = 0;

    for (int y = 0; y < 256; y++) {
        float s = dot16p(q, ks + y*16);
        float pr = fexp(s);
        sum += pr;
        u64 p2 = pack2(pr, pr);
        const ulonglong2* vp = (const ulonglong2*)(vs + y*16);
        ulonglong2 v0 = vp[0], v1 = vp[1], v2 = vp[2], v3 = vp[3];
        acc[0] = fma2(p2, v0.x, acc[0]);  acc[1] = fma2(p2, v0.y, acc[1]);
        acc[2] = fma2(p2, v1.x, acc[2]);  acc[3] = fma2(p2, v1.y, acc[3]);
        acc[4] = fma2(p2, v2.x, acc[4]);  acc[5] = fma2(p2, v2.y, acc[5]);
        acc[6] = fma2(p2, v3.x, acc[6]);  acc[7] = fma2(p2, v3.y, acc[7]);
    }
    float inv = 1.0f / sum;
    float* op = g_fout_t + (size_t)(b*TT + t) * (16*FF);
    #pragma unroll
    for (int c = 0; c < 8; c++) {
        float lo, hi; unpack2(acc[c], lo, hi);
        op[(2*c)*FF + tid]   = lo * inv;
        op[(2*c+1)*FF + tid] = hi * inv;
    }
}

// ---------------------------------------------------------------------------
// Kernel 5: time attention (causal). Block = (f, b); thread = t row.
// ---------------------------------------------------------------------------
__global__ __launch_bounds__(384) void k_tattn() {
    __shared__ float ks[384*16];   // kt   [y][c]
    __shared__ float vs[384*16];   // fout [y][c]
    int f = blockIdx.x, b = blockIdx.y;
    int tid = threadIdx.x;  // t

    const float* ktb = g_tqk  + (((size_t)b*32 + 16)*FF + f)*TT;
    const float* vb  = g_fout + (((size_t)b*16     )*FF + f)*TT;
    for (int i = tid; i < 6144; i += 384) {
        int c = i / 384, y = i % 384;
        ks[y*16 + c] = ktb[(size_t)c*NN + y];
        vs[y*16 + c] = vb [(size_t)c*NN + y];
    }
    u64 q[8];
    const float* qb = g_tqk + (((size_t)b*32)*FF + f)*TT;
    #pragma unroll
    for (int c = 0; c < 8; c++)
        q[c] = pack2(qb[(size_t)(2*c)*NN + tid] * 0.25f,
                     qb[(size_t)(2*c+1)*NN + tid] * 0.25f);
    __syncthreads();

    int t = tid;
    float sum = 0.f;
    u64 acc[8];
    #pragma unroll
    for (int c = 0; c < 8; c++) acc[c] = 0;

    for (int y = 0; y <= t; y++) {
        float s = dot16p(q, ks + y*16);
        float pr = fexp(s);
        sum += pr;
        u64 p2 = pack2(pr, pr);
        const ulonglong2* vp = (const ulonglong2*)(vs + y*16);
        ulonglong2 v0 = vp[0], v1 = vp[1], v2 = vp[2], v3 = vp[3];
        acc[0] = fma2(p2, v0.x, acc[0]);  acc[1] = fma2(p2, v0.y, acc[1]);
        acc[2] = fma2(p2, v1.x, acc[2]);  acc[3] = fma2(p2, v1.y, acc[3]);
        acc[4] = fma2(p2, v2.x, acc[4]);  acc[5] = fma2(p2, v2.y, acc[5]);
        acc[6] = fma2(p2, v3.x, acc[6]);  acc[7] = fma2(p2, v3.y, acc[7]);
    }
    float inv = 1.0f / sum;
    float* op = g_tout + (((size_t)b*16)*FF + f)*TT + t;
    #pragma unroll
    for (int c = 0; c < 8; c++) {
        float lo, hi; unpack2(acc[c], lo, hi);
        op[(size_t)(2*c)*NN]   = lo * inv;
        op[(size_t)(2*c+1)*NN] = hi * inv;
    }
}

// ---------------------------------------------------------------------------
// Kernel 6: proj conv1x1 (64<-16) + BN + PReLU + residual (packed FMA)
// ---------------------------------------------------------------------------
__global__ __launch_bounds__(256) void k_proj(
    const float* __restrict__ x,
    const float* __restrict__ pw, const float* __restrict__ pg,
    const float* __restrict__ pb, const float* __restrict__ pm,
    const float* __restrict__ pv, const float* __restrict__ pa,
    float* __restrict__ out)
{
    __shared__ float ws[64*16];
    __shared__ float sa[64], sbb[64], sal[64];
    int tid = threadIdx.x;
    for (int i = tid; i < 1024; i += 256) ws[i] = pw[i];
    if (tid < 64) {
        float a = pg[tid] * rsqrtf(pv[tid] + 1e-5f);
        sa[tid] = a; sbb[tid] = pb[tid] - pm[tid]*a; sal[tid] = pa[tid];
    }
    __syncthreads();

    size_t p   = (size_t)blockIdx.x*256 + tid;
    int    b   = (int)(p / NN);
    int    rem = (int)(p % NN);

    u64 tv[8];
    #pragma unroll
    for (int c = 0; c < 8; c++)
        tv[c] = pack2(g_tout[((size_t)b*16 + 2*c  )*NN + rem],
                      g_tout[((size_t)b*16 + 2*c+1)*NN + rem]);

    const float* xb = x   + (size_t)b*CC*NN + rem;
    float*       ob = out + (size_t)b*CC*NN + rem;
    for (int o = 0; o < 64; o++) {
        const ulonglong2* wp = (const ulonglong2*)(ws + o*16);
        ulonglong2 w0 = wp[0], w1 = wp[1], w2 = wp[2], w3 = wp[3];
        u64 a0 = fma2(tv[0], w0.x, 0), a1 = fma2(tv[1], w0.y, 0);
        a0 = fma2(tv[2], w1.x, a0);  a1 = fma2(tv[3], w1.y, a1);
        a0 = fma2(tv[4], w2.x, a0);  a1 = fma2(tv[5], w2.y, a1);
        a0 = fma2(tv[6], w3.x, a0);  a1 = fma2(tv[7], w3.y, a1);
        float acc = hsum2(add2(a0, a1));
        float yn = acc*sa[o] + sbb[o];
        float r  = yn >= 0.f ? yn : sal[o]*yn;
        ob[(size_t)o*NN] = r + xb[(size_t)o*NN];
    }
}

// ---------------------------------------------------------------------------
extern "C" void kernel_launch(void* const* d_in, const int* in_sizes, int n_in,
                              void* d_out, int out_size)
{
    const float* x   = (const float*)d_in[0];
    const float* fw  = (const float*)d_in[1];
    const float* fg  = (const float*)d_in[2];
    const float* fb  = (const float*)d_in[3];
    const float* fm  = (const float*)d_in[4];
    const float* fv  = (const float*)d_in[5];
    const float* fa  = (const float*)d_in[6];
    const float* tw  = (const float*)d_in[7];
    const float* tg  = (const float*)d_in[8];
    const float* tb  = (const float*)d_in[9];
    const float* tm  = (const float*)d_in[10];
    const float* tvv = (const float*)d_in[11];
    const float* ta  = (const float*)d_in[12];
    const float* pw  = (const float*)d_in[13];
    const float* pg  = (const float*)d_in[14];
    const float* pb  = (const float*)d_in[15];
    const float* pm  = (const float*)d_in[16];
    const float* pv  = (const float*)d_in[17];
    const float* pa  = (const float*)d_in[18];
    float*       out = (float*)d_out;

    // 1) fused qkv convs + BN + PReLU
    k_qkv<<<PP/256, 256>>>(x, fw, fg, fb, fm, fv, fa, tw, tg, tb, tm, tvv, ta);

    // 2) transpose fqkv: [b][cf][t] -> [b][t][cf]
    k_trans_qkv<<<dim3(384/32, 12288/32, BB), dim3(32,8)>>>();

    // 3) frequency attention
    k_fattn<<<dim3(TT, BB), 256>>>();

    // 4) transpose f_out: [b][t][cf] -> [b][cf][t]
    k_trans_fout<<<dim3(4096/32, 384/32, BB), dim3(32,8)>>>();

    // 5) time attention (causal)
    k_tattn<<<dim3(FF, BB), 384>>>();

    // 6) proj + BN + PReLU + residual
    k_proj<<<PP/256, 256>>>(x, pw, pg, pb, pm, pv, pa, out);
}